// round 7
// baseline (speedup 1.0000x reference)
#include <cuda_runtime.h>
#include <math.h>

#define L_TOT 1568
#define T_LEN 784
#define D_MODEL 768
#define N_HEADS 12
#define DIM_HEAD 64
#define D_FF 3072
#define BATCH 4
#define ROWS (BATCH * L_TOT)          // 6272
#define NPATCH 196

// ---------------- scratch ----------------
__device__ float g_xaug[ROWS * D_MODEL];
__device__ float g_h[ROWS * D_MODEL];
__device__ float g_qkv[ROWS * 3 * D_MODEL];
__device__ float g_ctx[ROWS * D_MODEL];
__device__ float g_y2[ROWS * D_MODEL];
__device__ float g_ff[ROWS * D_FF];

// ---------------- small helpers ----------------
__device__ __forceinline__ unsigned smem_u32(const void* p) {
    unsigned r;
    asm("{ .reg .u64 t; cvta.to.shared.u64 t, %1; cvt.u32.u64 %0, t; }" : "=r"(r) : "l"(p));
    return r;
}
__device__ __forceinline__ void cp16(unsigned dst, const void* src, bool valid) {
    int sz = valid ? 16 : 0;
    asm volatile("cp.async.cg.shared.global [%0], [%1], 16, %2;" :: "r"(dst), "l"(src), "r"(sz));
}
// raw f32 bits -> tf32 mma operand (HW uses top bits; truncation rounding)
__device__ __forceinline__ unsigned f2r(float f) { return __float_as_uint(f); }

__device__ __forceinline__ void mma_tf32(float4& d, const unsigned a[4], const unsigned b[2]) {
    asm volatile(
        "mma.sync.aligned.m16n8k8.row.col.f32.tf32.tf32.f32 "
        "{%0,%1,%2,%3}, {%4,%5,%6,%7}, {%8,%9}, {%0,%1,%2,%3};"
        : "+f"(d.x), "+f"(d.y), "+f"(d.z), "+f"(d.w)
        : "r"(a[0]), "r"(a[1]), "r"(a[2]), "r"(a[3]), "r"(b[0]), "r"(b[1]));
}

// ---------------- tf32 tensor-core GEMM (R3-proven structure, no cvt) ----------------
// C[m,n] = scale * sum_k A[m,k] * B[n,k]   (B row-major [N,K])
template <bool BIAS, bool RES, bool SILU, bool OUTW>
__global__ void __launch_bounds__(256, 1)
mma_gemm(const float* __restrict__ A, const float* __restrict__ B,
         float* __restrict__ C, const float* __restrict__ bias, const float* __restrict__ res,
         float* __restrict__ out2,
         int M, int N, int K, int lda, int ldb, int ldc, float scale) {
    const int BM = 128, BN = 128, BK = 16, PAD = 20;
    const int NT = 8;

    __shared__ float As[2][BM * PAD];
    __shared__ float Bs[2][BN * PAD];

    int tid = threadIdx.x;
    int m0 = blockIdx.y * BM, n0 = blockIdx.x * BN;
    int warp = tid >> 5, lane = tid & 31;
    int wm = warp & 3, wn = warp >> 2;
    int mw = m0 + wm * 32;
    int nw = n0 + wn * 64;
    int g = lane >> 2, tg = lane & 3;

    float4 acc[2][NT];
    #pragma unroll
    for (int i = 0; i < 2; i++)
        #pragma unroll
        for (int j = 0; j < NT; j++) acc[i][j] = make_float4(0.f, 0.f, 0.f, 0.f);

    unsigned sA = smem_u32(As), sB = smem_u32(Bs);

    auto load_stage = [&](int ks, int buf) {
        #pragma unroll
        for (int i = 0; i < 2; i++) {
            int c = tid + i * 256;
            int m = c >> 2, kc = (c & 3) << 2;
            unsigned dst = sA + (buf * BM * PAD + m * PAD + kc) * 4;
            cp16(dst, A + (long long)(m0 + m) * lda + ks + kc, (m0 + m) < M);
        }
        #pragma unroll
        for (int i = 0; i < 2; i++) {
            int c = tid + i * 256;
            int n = c >> 2, kc = (c & 3) << 2;
            unsigned dst = sB + (buf * BN * PAD + n * PAD + kc) * 4;
            cp16(dst, B + (long long)(n0 + n) * ldb + ks + kc, (n0 + n) < N);
        }
    };

    auto compute = [&](int buf) {
        const float* Ap = &As[0][buf * BM * PAD];
        const float* Bp = &Bs[0][buf * BN * PAD];
        #pragma unroll
        for (int ks = 0; ks < BK; ks += 8) {
            unsigned af[2][4];
            #pragma unroll
            for (int i = 0; i < 2; i++) {
                const float* p = Ap + (wm * 32 + i * 16 + g) * PAD + ks + tg;
                af[i][0] = f2r(p[0]);
                af[i][1] = f2r(p[8 * PAD]);
                af[i][2] = f2r(p[4]);
                af[i][3] = f2r(p[8 * PAD + 4]);
            }
            unsigned bf[NT][2];
            #pragma unroll
            for (int j = 0; j < NT; j++) {
                const float* p = Bp + (wn * 64 + j * 8 + g) * PAD + ks + tg;
                bf[j][0] = f2r(p[0]);
                bf[j][1] = f2r(p[4]);
            }
            #pragma unroll
            for (int i = 0; i < 2; i++)
                #pragma unroll
                for (int j = 0; j < NT; j++)
                    mma_tf32(acc[i][j], af[i], bf[j]);
        }
    };

    int numK = K / BK;
    load_stage(0, 0);
    asm volatile("cp.async.commit_group;");
    for (int it = 0; it < numK; it++) {
        if (it + 1 < numK) {
            load_stage((it + 1) * BK, (it + 1) & 1);
            asm volatile("cp.async.commit_group;");
            asm volatile("cp.async.wait_group 1;");
        } else {
            asm volatile("cp.async.wait_group 0;");
        }
        __syncthreads();
        compute(it & 1);
        __syncthreads();
    }

    #pragma unroll
    for (int i = 0; i < 2; i++) {
        #pragma unroll
        for (int half = 0; half < 2; half++) {
            int r = mw + i * 16 + g + half * 8;
            if (r >= M) continue;
            long long base = (long long)r * ldc;
            int bb, l;
            if (OUTW) { bb = r / L_TOT; l = r - bb * L_TOT; }
            #pragma unroll
            for (int j = 0; j < NT; j++) {
                float v0 = half ? acc[i][j].z : acc[i][j].x;
                float v1 = half ? acc[i][j].w : acc[i][j].y;
                int c0 = nw + j * 8 + tg * 2;
                float w0 = v0 * scale, w1 = v1 * scale;
                if (BIAS) { w0 += bias[c0]; w1 += bias[c0 + 1]; }
                if (SILU) {
                    w0 = w0 / (1.f + expf(-w0));
                    w1 = w1 / (1.f + expf(-w1));
                }
                if (RES) { w0 += res[base + c0]; w1 += res[base + c0 + 1]; }
                if (c0 < N)     C[base + c0] = w0;
                if (c0 + 1 < N) C[base + c0 + 1] = w1;
                if (OUTW && l >= T_LEN) {
                    long long ob = ((long long)bb * T_LEN + (l - T_LEN)) * D_MODEL;
                    if (c0 < N)     out2[ob + c0] = w0;
                    if (c0 + 1 < N) out2[ob + c0 + 1] = w1;
                }
            }
        }
    }
}

// ---------------- fused flash attention (no cvt anywhere) ----------------
#define PADQ 68
__global__ void __launch_bounds__(256, 1)
flash_attn(const float* __restrict__ qkv, float* __restrict__ ctx) {
    extern __shared__ float sm[];
    float* sP = sm;                        // 128 * PADQ
    float* sK = sm + 128 * PADQ;           // 2 * 64 * PADQ
    float* sV = sK + 2 * 64 * PADQ;        // 2 * 64 * PADQ

    int tid = threadIdx.x;
    int warp = tid >> 5, lane = tid & 31;
    int g = lane >> 2, tg = lane & 3;
    int bh = blockIdx.y;
    int b = bh / N_HEADS, h = bh - b * N_HEADS;
    int m0 = blockIdx.x * 128;

    const float* base = qkv + (long long)b * L_TOT * (3 * D_MODEL);
    const float* Qp = base + h * 64;
    const float* Kp = base + D_MODEL + h * 64;
    const float* Vp = base + 2 * D_MODEL + h * 64;

    #pragma unroll
    for (int i = 0; i < 8; i++) {
        int c = tid + i * 256;
        int m = c >> 4, dc = (c & 15) << 2;
        unsigned dst = smem_u32(sP + m * PADQ + dc);
        cp16(dst, Qp + (long long)(m0 + m) * (3 * D_MODEL) + dc, (m0 + m) < L_TOT);
    }
    asm volatile("cp.async.commit_group;");
    asm volatile("cp.async.wait_group 0;");
    __syncthreads();

    unsigned qf[8][4];
    {
        const float* qp = sP + (warp * 16) * PADQ;
        #pragma unroll
        for (int ks = 0; ks < 8; ks++) {
            qf[ks][0] = f2r(qp[g * PADQ + 8 * ks + tg]);
            qf[ks][1] = f2r(qp[(g + 8) * PADQ + 8 * ks + tg]);
            qf[ks][2] = f2r(qp[g * PADQ + 8 * ks + tg + 4]);
            qf[ks][3] = f2r(qp[(g + 8) * PADQ + 8 * ks + tg + 4]);
        }
    }
    __syncthreads();

    int r0 = m0 + warp * 16 + g;
    int r1 = r0 + 8;
    int km0 = (r0 < T_LEN) ? L_TOT : ((r0 / NPATCH) + 1) * NPATCH;
    int km1 = (r1 < T_LEN) ? L_TOT : ((r1 / NPATCH) + 1) * NPATCH;

    float mrow0 = -1e30f, mrow1 = -1e30f, lrow0 = 0.f, lrow1 = 0.f;
    float4 accO[8];
    #pragma unroll
    for (int j = 0; j < 8; j++) accO[j] = make_float4(0.f, 0.f, 0.f, 0.f);

    int rlast = min(m0 + 127, L_TOT - 1);
    int kend = (m0 < T_LEN) ? L_TOT : ((rlast / NPATCH) + 1) * NPATCH;
    int ntiles = (kend + 63) >> 6;

    auto loadKV = [&](int t, int buf) {
        int n0t = t * 64;
        #pragma unroll
        for (int i = 0; i < 4; i++) {
            int c = tid + i * 256;
            int kv = c >> 4, dc = (c & 15) << 2;
            bool ok = (n0t + kv) < L_TOT;
            long long goff = (long long)(n0t + kv) * (3 * D_MODEL) + dc;
            cp16(smem_u32(sK + buf * 64 * PADQ + kv * PADQ + dc), Kp + goff, ok);
            cp16(smem_u32(sV + buf * 64 * PADQ + kv * PADQ + dc), Vp + goff, ok);
        }
    };

    loadKV(0, 0);
    asm volatile("cp.async.commit_group;");

    float* pp = sP + (warp * 16) * PADQ;

    for (int t = 0; t < ntiles; t++) {
        int buf = t & 1;
        if (t + 1 < ntiles) {
            loadKV(t + 1, buf ^ 1);
            asm volatile("cp.async.commit_group;");
            asm volatile("cp.async.wait_group 1;");
        } else {
            asm volatile("cp.async.wait_group 0;");
        }
        __syncthreads();

        float4 s[8];
        #pragma unroll
        for (int j = 0; j < 8; j++) s[j] = make_float4(0.f, 0.f, 0.f, 0.f);
        const unsigned* kb = (const unsigned*)(sK + buf * 64 * PADQ);
        #pragma unroll
        for (int j = 0; j < 8; j++) {
            const unsigned* kr = kb + (8 * j + g) * PADQ;
            #pragma unroll
            for (int ks = 0; ks < 8; ks++) {
                unsigned bf[2];
                bf[0] = kr[8 * ks + tg];
                bf[1] = kr[8 * ks + tg + 4];
                mma_tf32(s[j], qf[ks], bf);
            }
        }

        float tmax0 = -1e30f, tmax1 = -1e30f;
        #pragma unroll
        for (int j = 0; j < 8; j++) {
            int c0 = t * 64 + 8 * j + 2 * tg;
            int c1 = c0 + 1;
            s[j].x = (c0 < km0) ? s[j].x * 0.125f : -1e30f;
            s[j].y = (c1 < km0) ? s[j].y * 0.125f : -1e30f;
            s[j].z = (c0 < km1) ? s[j].z * 0.125f : -1e30f;
            s[j].w = (c1 < km1) ? s[j].w * 0.125f : -1e30f;
            tmax0 = fmaxf(tmax0, fmaxf(s[j].x, s[j].y));
            tmax1 = fmaxf(tmax1, fmaxf(s[j].z, s[j].w));
        }
        tmax0 = fmaxf(tmax0, __shfl_xor_sync(0xffffffffu, tmax0, 1));
        tmax0 = fmaxf(tmax0, __shfl_xor_sync(0xffffffffu, tmax0, 2));
        tmax1 = fmaxf(tmax1, __shfl_xor_sync(0xffffffffu, tmax1, 1));
        tmax1 = fmaxf(tmax1, __shfl_xor_sync(0xffffffffu, tmax1, 2));

        float mn0 = fmaxf(mrow0, tmax0), mn1 = fmaxf(mrow1, tmax1);
        float al0 = __expf(mrow0 - mn0), al1 = __expf(mrow1 - mn1);
        mrow0 = mn0; mrow1 = mn1;

        float rs0 = 0.f, rs1 = 0.f;
        #pragma unroll
        for (int j = 0; j < 8; j++) {
            s[j].x = __expf(s[j].x - mn0);
            s[j].y = __expf(s[j].y - mn0);
            s[j].z = __expf(s[j].z - mn1);
            s[j].w = __expf(s[j].w - mn1);
            rs0 += s[j].x + s[j].y;
            rs1 += s[j].z + s[j].w;
            *(float2*)&pp[g * PADQ + 8 * j + 2 * tg] = make_float2(s[j].x, s[j].y);
            *(float2*)&pp[(g + 8) * PADQ + 8 * j + 2 * tg] = make_float2(s[j].z, s[j].w);
        }
        rs0 += __shfl_xor_sync(0xffffffffu, rs0, 1);
        rs0 += __shfl_xor_sync(0xffffffffu, rs0, 2);
        rs1 += __shfl_xor_sync(0xffffffffu, rs1, 1);
        rs1 += __shfl_xor_sync(0xffffffffu, rs1, 2);
        lrow0 = lrow0 * al0 + rs0;
        lrow1 = lrow1 * al1 + rs1;

        #pragma unroll
        for (int j = 0; j < 8; j++) {
            accO[j].x *= al0; accO[j].y *= al0;
            accO[j].z *= al1; accO[j].w *= al1;
        }
        __syncwarp();

        const unsigned* ppu = (const unsigned*)pp;
        const unsigned* vb = (const unsigned*)(sV + buf * 64 * PADQ);
        #pragma unroll
        for (int ks = 0; ks < 8; ks++) {
            unsigned af[4];
            af[0] = ppu[g * PADQ + 8 * ks + tg];
            af[1] = ppu[(g + 8) * PADQ + 8 * ks + tg];
            af[2] = ppu[g * PADQ + 8 * ks + tg + 4];
            af[3] = ppu[(g + 8) * PADQ + 8 * ks + tg + 4];
            const unsigned* v0 = vb + (8 * ks + tg) * PADQ;
            const unsigned* v1 = vb + (8 * ks + tg + 4) * PADQ;
            #pragma unroll
            for (int j = 0; j < 8; j++) {
                unsigned bf[2];
                bf[0] = v0[8 * j + g];
                bf[1] = v1[8 * j + g];
                mma_tf32(accO[j], af, bf);
            }
        }
        __syncthreads();
    }

    float inv0 = 1.f / lrow0, inv1 = 1.f / lrow1;
    if (r0 < L_TOT) {
        float* op = ctx + ((long long)b * L_TOT + r0) * D_MODEL + h * 64;
        #pragma unroll
        for (int j = 0; j < 8; j++)
            *(float2*)&op[8 * j + 2 * tg] = make_float2(accO[j].x * inv0, accO[j].y * inv0);
    }
    if (r1 < L_TOT) {
        float* op = ctx + ((long long)b * L_TOT + r1) * D_MODEL + h * 64;
        #pragma unroll
        for (int j = 0; j < 8; j++)
            *(float2*)&op[8 * j + 2 * tg] = make_float2(accO[j].z * inv1, accO[j].w * inv1);
    }
}

// ---------------- layernorms ----------------
__device__ __forceinline__ void block_reduce2(float& a, float& b, float* s1, float* s2) {
    int tid = threadIdx.x;
    s1[tid] = a; s2[tid] = b; __syncthreads();
    #pragma unroll
    for (int s = 128; s; s >>= 1) {
        if (tid < s) { s1[tid] += s1[tid + s]; s2[tid] += s2[tid + s]; }
        __syncthreads();
    }
    a = s1[0]; b = s2[0]; __syncthreads();
}

__global__ void ln_build_kernel(const float* __restrict__ x,
                                const float* __restrict__ mem,
                                const float* __restrict__ g1, const float* __restrict__ b1,
                                const float* __restrict__ ga, const float* __restrict__ ba) {
    __shared__ float s1[256], s2[256];
    int row = blockIdx.x;
    int b = row / L_TOT;
    int l = row - b * L_TOT;
    const float* src = (l < T_LEN)
        ? mem + ((long long)b * 1024 + l) * D_MODEL
        : x   + ((long long)b * T_LEN + (l - T_LEN)) * D_MODEL;
    int tid = threadIdx.x;
    float v[3]; float sum = 0.f, sq = 0.f;
    #pragma unroll
    for (int i = 0; i < 3; i++) {
        v[i] = src[tid + 256 * i];
        sum += v[i]; sq += v[i] * v[i];
    }
    block_reduce2(sum, sq, s1, s2);
    float mu = sum * (1.f / 768.f);
    float var = sq * (1.f / 768.f) - mu * mu;
    float rstd = rsqrtf(var + 1e-5f);

    float w[3]; sum = 0.f; sq = 0.f;
    #pragma unroll
    for (int i = 0; i < 3; i++) {
        int idx = tid + 256 * i;
        w[i] = (v[i] - mu) * rstd * g1[idx] + b1[idx];
        g_xaug[(long long)row * D_MODEL + idx] = w[i];
        sum += w[i]; sq += w[i] * w[i];
    }
    block_reduce2(sum, sq, s1, s2);
    float mu2 = sum * (1.f / 768.f);
    float var2 = sq * (1.f / 768.f) - mu2 * mu2;
    float rstd2 = rsqrtf(var2 + 1e-5f);
    #pragma unroll
    for (int i = 0; i < 3; i++) {
        int idx = tid + 256 * i;
        g_h[(long long)row * D_MODEL + idx] = (w[i] - mu2) * rstd2 * ga[idx] + ba[idx];
    }
}

__global__ void ln_kernel(const float* __restrict__ src, float* __restrict__ dst,
                          const float* __restrict__ g, const float* __restrict__ b) {
    __shared__ float s1[256], s2[256];
    int row = blockIdx.x;
    int tid = threadIdx.x;
    const float* p = src + (long long)row * D_MODEL;
    float v[3]; float sum = 0.f, sq = 0.f;
    #pragma unroll
    for (int i = 0; i < 3; i++) {
        v[i] = p[tid + 256 * i];
        sum += v[i]; sq += v[i] * v[i];
    }
    block_reduce2(sum, sq, s1, s2);
    float mu = sum * (1.f / 768.f);
    float var = sq * (1.f / 768.f) - mu * mu;
    float rstd = rsqrtf(var + 1e-5f);
    #pragma unroll
    for (int i = 0; i < 3; i++) {
        int idx = tid + 256 * i;
        dst[(long long)row * D_MODEL + idx] = (v[i] - mu) * rstd * g[idx] + b[idx];
    }
}

// ---------------- launch ----------------
extern "C" void kernel_launch(void* const* d_in, const int* in_sizes, int n_in,
                              void* d_out, int out_size) {
    const float* x        = (const float*)d_in[0];
    const float* memory   = (const float*)d_in[1];
    const float* ln_att_g = (const float*)d_in[2];
    const float* ln_att_b = (const float*)d_in[3];
    const float* w_qkv    = (const float*)d_in[4];
    const float* w_out    = (const float*)d_in[5];
    const float* b_out    = (const float*)d_in[6];
    const float* ln1_g    = (const float*)d_in[7];
    const float* ln1_b    = (const float*)d_in[8];
    const float* ln2_g    = (const float*)d_in[9];
    const float* ln2_b    = (const float*)d_in[10];
    const float* w1       = (const float*)d_in[11];
    const float* b1       = (const float*)d_in[12];
    const float* w2       = (const float*)d_in[13];
    const float* b2       = (const float*)d_in[14];
    float* out = (float*)d_out;

    float *xaug, *h, *qkv, *ctx, *y2, *ff;
    cudaGetSymbolAddress((void**)&xaug, g_xaug);
    cudaGetSymbolAddress((void**)&h,    g_h);
    cudaGetSymbolAddress((void**)&qkv,  g_qkv);
    cudaGetSymbolAddress((void**)&ctx,  g_ctx);
    cudaGetSymbolAddress((void**)&y2,   g_y2);
    cudaGetSymbolAddress((void**)&ff,   g_ff);

    const int FLASH_SMEM = (128 * PADQ + 4 * 64 * PADQ) * 4;  // 104448 B
    cudaFuncSetAttribute(flash_attn, cudaFuncAttributeMaxDynamicSharedMemorySize, FLASH_SMEM);

    // 1) x_aug = ln1(concat(mem, x)); h = ln_att(x_aug)
    ln_build_kernel<<<ROWS, 256>>>(x, memory, ln1_g, ln1_b, ln_att_g, ln_att_b);

    // 2) qkv = h @ w_qkv^T
    mma_gemm<false, false, false, false><<<dim3(18, 49), 256>>>(
        h, w_qkv, qkv, nullptr, nullptr, nullptr,
        ROWS, 3 * D_MODEL, D_MODEL, D_MODEL, D_MODEL, 3 * D_MODEL, 1.f);

    // 3-5) fused attention -> ctx
    flash_attn<<<dim3(13, 48), 256, FLASH_SMEM>>>(qkv, ctx);

    // 6) xaug += ctx @ w_out^T + b_out
    mma_gemm<true, true, false, false><<<dim3(6, 49), 256>>>(
        ctx, w_out, xaug, b_out, xaug, nullptr,
        ROWS, D_MODEL, D_MODEL, D_MODEL, D_MODEL, D_MODEL, 1.f);

    // 7) y2 = ln2(xaug)
    ln_kernel<<<ROWS, 256>>>(xaug, y2, ln2_g, ln2_b);

    // 8) ff = silu(y2 @ w1^T + b1)
    mma_gemm<true, false, true, false><<<dim3(24, 49), 256>>>(
        y2, w1, ff, b1, nullptr, nullptr,
        ROWS, D_FF, D_MODEL, D_MODEL, D_MODEL, D_FF, 1.f);

    // 9) xaug += ff @ w2^T + b2 ; scatter x-rows to out
    mma_gemm<true, true, false, true><<<dim3(6, 49), 256>>>(
        ff, w2, xaug, b2, xaug, out,
        ROWS, D_MODEL, D_FF, D_FF, D_FF, D_MODEL, 1.f);
}

// round 8
// speedup vs baseline: 1.1205x; 1.1205x over previous
#include <cuda_runtime.h>
#include <math.h>

#define L_TOT 1568
#define T_LEN 784
#define D_MODEL 768
#define N_HEADS 12
#define DIM_HEAD 64
#define D_FF 3072
#define BATCH 4
#define ROWS (BATCH * L_TOT)          // 6272
#define NPATCH 196

// ---------------- scratch ----------------
__device__ float g_xaug[ROWS * D_MODEL];
__device__ float g_h[ROWS * D_MODEL];
__device__ float g_qkv[ROWS * 3 * D_MODEL];
__device__ float g_ctx[ROWS * D_MODEL];
__device__ float g_y2[ROWS * D_MODEL];
__device__ float g_ff[ROWS * D_FF];

// ---------------- small helpers ----------------
__device__ __forceinline__ unsigned smem_u32(const void* p) {
    unsigned r;
    asm("{ .reg .u64 t; cvta.to.shared.u64 t, %1; cvt.u32.u64 %0, t; }" : "=r"(r) : "l"(p));
    return r;
}
__device__ __forceinline__ void cp16(unsigned dst, const void* src, bool valid) {
    int sz = valid ? 16 : 0;
    asm volatile("cp.async.cg.shared.global [%0], [%1], 16, %2;" :: "r"(dst), "l"(src), "r"(sz));
}
__device__ __forceinline__ unsigned f2tf(float f) {
    unsigned u;
    asm("cvt.rna.tf32.f32 %0, %1;" : "=r"(u) : "f"(f));
    return u;
}
__device__ __forceinline__ void mma_tf32(float4& d, const unsigned a[4], const unsigned b[2]) {
    asm volatile(
        "mma.sync.aligned.m16n8k8.row.col.f32.tf32.tf32.f32 "
        "{%0,%1,%2,%3}, {%4,%5,%6,%7}, {%8,%9}, {%0,%1,%2,%3};"
        : "+f"(d.x), "+f"(d.y), "+f"(d.z), "+f"(d.w)
        : "r"(a[0]), "r"(a[1]), "r"(a[2]), "r"(a[3]), "r"(b[0]), "r"(b[1]));
}

// ---------------- tf32 tensor-core GEMM (exact R3 structure) ----------------
// C[m,n] = scale * sum_k A[m,k] * B[n,k]   (B row-major [N,K])
// Epilogue: +bias[n]; silu; +res; optional scatter of x-rows to out.
template <bool BIAS, bool RES, bool SILU, bool OUTW>
__global__ void __launch_bounds__(256, 1)
mma_gemm(const float* __restrict__ A, const float* __restrict__ B,
         float* __restrict__ C, const float* __restrict__ bias, const float* __restrict__ res,
         float* __restrict__ out2,
         int M, int N, int K, int lda, int ldb, int ldc, float scale) {
    const int BM = 128, BN = 128, BK = 16, PAD = 20;
    const int NT = 8;

    __shared__ float As[2][BM * PAD];
    __shared__ float Bs[2][BN * PAD];

    int tid = threadIdx.x;
    int m0 = blockIdx.y * BM, n0 = blockIdx.x * BN;
    int warp = tid >> 5, lane = tid & 31;
    int wm = warp & 3, wn = warp >> 2;
    int mw = m0 + wm * 32;
    int nw = n0 + wn * 64;
    int g = lane >> 2, tg = lane & 3;

    float4 acc[2][NT];
    #pragma unroll
    for (int i = 0; i < 2; i++)
        #pragma unroll
        for (int j = 0; j < NT; j++) acc[i][j] = make_float4(0.f, 0.f, 0.f, 0.f);

    unsigned sA = smem_u32(As), sB = smem_u32(Bs);

    auto load_stage = [&](int ks, int buf) {
        #pragma unroll
        for (int i = 0; i < 2; i++) {
            int c = tid + i * 256;
            int m = c >> 2, kc = (c & 3) << 2;
            unsigned dst = sA + (buf * BM * PAD + m * PAD + kc) * 4;
            cp16(dst, A + (long long)(m0 + m) * lda + ks + kc, (m0 + m) < M);
        }
        #pragma unroll
        for (int i = 0; i < 2; i++) {
            int c = tid + i * 256;
            int n = c >> 2, kc = (c & 3) << 2;
            unsigned dst = sB + (buf * BN * PAD + n * PAD + kc) * 4;
            cp16(dst, B + (long long)(n0 + n) * ldb + ks + kc, (n0 + n) < N);
        }
    };

    auto compute = [&](int buf) {
        const float* Ap = &As[0][buf * BM * PAD];
        const float* Bp = &Bs[0][buf * BN * PAD];
        #pragma unroll
        for (int ks = 0; ks < BK; ks += 8) {
            unsigned af[2][4];
            #pragma unroll
            for (int i = 0; i < 2; i++) {
                const float* p = Ap + (wm * 32 + i * 16 + g) * PAD + ks + tg;
                af[i][0] = f2tf(p[0]);
                af[i][1] = f2tf(p[8 * PAD]);
                af[i][2] = f2tf(p[4]);
                af[i][3] = f2tf(p[8 * PAD + 4]);
            }
            unsigned bf[NT][2];
            #pragma unroll
            for (int j = 0; j < NT; j++) {
                const float* p = Bp + (wn * 64 + j * 8 + g) * PAD + ks + tg;
                bf[j][0] = f2tf(p[0]);
                bf[j][1] = f2tf(p[4]);
            }
            #pragma unroll
            for (int i = 0; i < 2; i++)
                #pragma unroll
                for (int j = 0; j < NT; j++)
                    mma_tf32(acc[i][j], af[i], bf[j]);
        }
    };

    int numK = K / BK;
    load_stage(0, 0);
    asm volatile("cp.async.commit_group;");
    for (int it = 0; it < numK; it++) {
        if (it + 1 < numK) {
            load_stage((it + 1) * BK, (it + 1) & 1);
            asm volatile("cp.async.commit_group;");
            asm volatile("cp.async.wait_group 1;");
        } else {
            asm volatile("cp.async.wait_group 0;");
        }
        __syncthreads();
        compute(it & 1);
        __syncthreads();
    }

    #pragma unroll
    for (int i = 0; i < 2; i++) {
        #pragma unroll
        for (int half = 0; half < 2; half++) {
            int r = mw + i * 16 + g + half * 8;
            if (r >= M) continue;
            long long base = (long long)r * ldc;
            int bb, l;
            if (OUTW) { bb = r / L_TOT; l = r - bb * L_TOT; }
            #pragma unroll
            for (int j = 0; j < NT; j++) {
                float v0 = half ? acc[i][j].z : acc[i][j].x;
                float v1 = half ? acc[i][j].w : acc[i][j].y;
                int c0 = nw + j * 8 + tg * 2;
                float w0 = v0 * scale, w1 = v1 * scale;
                if (BIAS) { w0 += bias[c0]; w1 += bias[c0 + 1]; }
                if (SILU) {
                    w0 = w0 / (1.f + expf(-w0));
                    w1 = w1 / (1.f + expf(-w1));
                }
                if (RES) { w0 += res[base + c0]; w1 += res[base + c0 + 1]; }
                if (c0 < N)     C[base + c0] = w0;
                if (c0 + 1 < N) C[base + c0 + 1] = w1;
                if (OUTW && l >= T_LEN) {
                    long long ob = ((long long)bb * T_LEN + (l - T_LEN)) * D_MODEL;
                    if (c0 < N)     out2[ob + c0] = w0;
                    if (c0 + 1 < N) out2[ob + c0 + 1] = w1;
                }
            }
        }
    }
}

// ---------------- fused flash attention (R3 math, 2 CTAs/SM) ----------------
#define PADQ 68
__global__ void __launch_bounds__(256, 2)
flash_attn(const float* __restrict__ qkv, float* __restrict__ ctx) {
    extern __shared__ float sm[];
    float* sP = sm;                        // 128 * PADQ
    float* sK = sm + 128 * PADQ;           // 2 * 64 * PADQ
    float* sV = sK + 2 * 64 * PADQ;        // 2 * 64 * PADQ

    int tid = threadIdx.x;
    int warp = tid >> 5, lane = tid & 31;
    int g = lane >> 2, tg = lane & 3;
    int bh = blockIdx.y;
    int b = bh / N_HEADS, h = bh - b * N_HEADS;
    int m0 = blockIdx.x * 128;

    const float* base = qkv + (long long)b * L_TOT * (3 * D_MODEL);
    const float* Qp = base + h * 64;
    const float* Kp = base + D_MODEL + h * 64;
    const float* Vp = base + 2 * D_MODEL + h * 64;

    #pragma unroll
    for (int i = 0; i < 8; i++) {
        int c = tid + i * 256;
        int m = c >> 4, dc = (c & 15) << 2;
        unsigned dst = smem_u32(sP + m * PADQ + dc);
        cp16(dst, Qp + (long long)(m0 + m) * (3 * D_MODEL) + dc, (m0 + m) < L_TOT);
    }
    asm volatile("cp.async.commit_group;");
    asm volatile("cp.async.wait_group 0;");
    __syncthreads();

    unsigned qf[8][4];
    {
        const float* qp = sP + (warp * 16) * PADQ;
        #pragma unroll
        for (int ks = 0; ks < 8; ks++) {
            qf[ks][0] = f2tf(qp[g * PADQ + 8 * ks + tg]);
            qf[ks][1] = f2tf(qp[(g + 8) * PADQ + 8 * ks + tg]);
            qf[ks][2] = f2tf(qp[g * PADQ + 8 * ks + tg + 4]);
            qf[ks][3] = f2tf(qp[(g + 8) * PADQ + 8 * ks + tg + 4]);
        }
    }
    __syncthreads();

    int r0 = m0 + warp * 16 + g;
    int r1 = r0 + 8;
    int km0 = (r0 < T_LEN) ? L_TOT : ((r0 / NPATCH) + 1) * NPATCH;
    int km1 = (r1 < T_LEN) ? L_TOT : ((r1 / NPATCH) + 1) * NPATCH;

    float mrow0 = -1e30f, mrow1 = -1e30f, lrow0 = 0.f, lrow1 = 0.f;
    float4 accO[8];
    #pragma unroll
    for (int j = 0; j < 8; j++) accO[j] = make_float4(0.f, 0.f, 0.f, 0.f);

    int rlast = min(m0 + 127, L_TOT - 1);
    int kend = (m0 < T_LEN) ? L_TOT : ((rlast / NPATCH) + 1) * NPATCH;
    int ntiles = (kend + 63) >> 6;

    auto loadKV = [&](int t, int buf) {
        int n0t = t * 64;
        #pragma unroll
        for (int i = 0; i < 4; i++) {
            int c = tid + i * 256;
            int kv = c >> 4, dc = (c & 15) << 2;
            bool ok = (n0t + kv) < L_TOT;
            long long goff = (long long)(n0t + kv) * (3 * D_MODEL) + dc;
            cp16(smem_u32(sK + buf * 64 * PADQ + kv * PADQ + dc), Kp + goff, ok);
            cp16(smem_u32(sV + buf * 64 * PADQ + kv * PADQ + dc), Vp + goff, ok);
        }
    };

    loadKV(0, 0);
    asm volatile("cp.async.commit_group;");

    float* pp = sP + (warp * 16) * PADQ;

    for (int t = 0; t < ntiles; t++) {
        int buf = t & 1;
        if (t + 1 < ntiles) {
            loadKV(t + 1, buf ^ 1);
            asm volatile("cp.async.commit_group;");
            asm volatile("cp.async.wait_group 1;");
        } else {
            asm volatile("cp.async.wait_group 0;");
        }
        __syncthreads();

        float4 s[8];
        #pragma unroll
        for (int j = 0; j < 8; j++) s[j] = make_float4(0.f, 0.f, 0.f, 0.f);
        const float* kb = sK + buf * 64 * PADQ;
        #pragma unroll
        for (int j = 0; j < 8; j++) {
            const float* kr = kb + (8 * j + g) * PADQ;
            #pragma unroll
            for (int ks = 0; ks < 8; ks++) {
                unsigned bf[2];
                bf[0] = f2tf(kr[8 * ks + tg]);
                bf[1] = f2tf(kr[8 * ks + tg + 4]);
                mma_tf32(s[j], qf[ks], bf);
            }
        }

        float tmax0 = -1e30f, tmax1 = -1e30f;
        #pragma unroll
        for (int j = 0; j < 8; j++) {
            int c0 = t * 64 + 8 * j + 2 * tg;
            int c1 = c0 + 1;
            s[j].x = (c0 < km0) ? s[j].x * 0.125f : -1e30f;
            s[j].y = (c1 < km0) ? s[j].y * 0.125f : -1e30f;
            s[j].z = (c0 < km1) ? s[j].z * 0.125f : -1e30f;
            s[j].w = (c1 < km1) ? s[j].w * 0.125f : -1e30f;
            tmax0 = fmaxf(tmax0, fmaxf(s[j].x, s[j].y));
            tmax1 = fmaxf(tmax1, fmaxf(s[j].z, s[j].w));
        }
        tmax0 = fmaxf(tmax0, __shfl_xor_sync(0xffffffffu, tmax0, 1));
        tmax0 = fmaxf(tmax0, __shfl_xor_sync(0xffffffffu, tmax0, 2));
        tmax1 = fmaxf(tmax1, __shfl_xor_sync(0xffffffffu, tmax1, 1));
        tmax1 = fmaxf(tmax1, __shfl_xor_sync(0xffffffffu, tmax1, 2));

        float mn0 = fmaxf(mrow0, tmax0), mn1 = fmaxf(mrow1, tmax1);
        float al0 = __expf(mrow0 - mn0), al1 = __expf(mrow1 - mn1);
        mrow0 = mn0; mrow1 = mn1;

        float rs0 = 0.f, rs1 = 0.f;
        #pragma unroll
        for (int j = 0; j < 8; j++) {
            s[j].x = __expf(s[j].x - mn0);
            s[j].y = __expf(s[j].y - mn0);
            s[j].z = __expf(s[j].z - mn1);
            s[j].w = __expf(s[j].w - mn1);
            rs0 += s[j].x + s[j].y;
            rs1 += s[j].z + s[j].w;
            *(float2*)&pp[g * PADQ + 8 * j + 2 * tg] = make_float2(s[j].x, s[j].y);
            *(float2*)&pp[(g + 8) * PADQ + 8 * j + 2 * tg] = make_float2(s[j].z, s[j].w);
        }
        rs0 += __shfl_xor_sync(0xffffffffu, rs0, 1);
        rs0 += __shfl_xor_sync(0xffffffffu, rs0, 2);
        rs1 += __shfl_xor_sync(0xffffffffu, rs1, 1);
        rs1 += __shfl_xor_sync(0xffffffffu, rs1, 2);
        lrow0 = lrow0 * al0 + rs0;
        lrow1 = lrow1 * al1 + rs1;

        #pragma unroll
        for (int j = 0; j < 8; j++) {
            accO[j].x *= al0; accO[j].y *= al0;
            accO[j].z *= al1; accO[j].w *= al1;
        }
        __syncwarp();

        const float* vb = sV + buf * 64 * PADQ;
        #pragma unroll
        for (int ks = 0; ks < 8; ks++) {
            unsigned af[4];
            af[0] = f2tf(pp[g * PADQ + 8 * ks + tg]);
            af[1] = f2tf(pp[(g + 8) * PADQ + 8 * ks + tg]);
            af[2] = f2tf(pp[g * PADQ + 8 * ks + tg + 4]);
            af[3] = f2tf(pp[(g + 8) * PADQ + 8 * ks + tg + 4]);
            const float* v0 = vb + (8 * ks + tg) * PADQ;
            const float* v1 = vb + (8 * ks + tg + 4) * PADQ;
            #pragma unroll
            for (int j = 0; j < 8; j++) {
                unsigned bf[2];
                bf[0] = f2tf(v0[8 * j + g]);
                bf[1] = f2tf(v1[8 * j + g]);
                mma_tf32(accO[j], af, bf);
            }
        }
        __syncthreads();
    }

    float inv0 = 1.f / lrow0, inv1 = 1.f / lrow1;
    if (r0 < L_TOT) {
        float* op = ctx + ((long long)b * L_TOT + r0) * D_MODEL + h * 64;
        #pragma unroll
        for (int j = 0; j < 8; j++)
            *(float2*)&op[8 * j + 2 * tg] = make_float2(accO[j].x * inv0, accO[j].y * inv0);
    }
    if (r1 < L_TOT) {
        float* op = ctx + ((long long)b * L_TOT + r1) * D_MODEL + h * 64;
        #pragma unroll
        for (int j = 0; j < 8; j++)
            *(float2*)&op[8 * j + 2 * tg] = make_float2(accO[j].z * inv1, accO[j].w * inv1);
    }
}

// ---------------- layernorms ----------------
__device__ __forceinline__ void block_reduce2(float& a, float& b, float* s1, float* s2) {
    int tid = threadIdx.x;
    s1[tid] = a; s2[tid] = b; __syncthreads();
    #pragma unroll
    for (int s = 128; s; s >>= 1) {
        if (tid < s) { s1[tid] += s1[tid + s]; s2[tid] += s2[tid + s]; }
        __syncthreads();
    }
    a = s1[0]; b = s2[0]; __syncthreads();
}

__global__ void ln_build_kernel(const float* __restrict__ x,
                                const float* __restrict__ mem,
                                const float* __restrict__ g1, const float* __restrict__ b1,
                                const float* __restrict__ ga, const float* __restrict__ ba) {
    __shared__ float s1[256], s2[256];
    int row = blockIdx.x;
    int b = row / L_TOT;
    int l = row - b * L_TOT;
    const float* src = (l < T_LEN)
        ? mem + ((long long)b * 1024 + l) * D_MODEL
        : x   + ((long long)b * T_LEN + (l - T_LEN)) * D_MODEL;
    int tid = threadIdx.x;
    float v[3]; float sum = 0.f, sq = 0.f;
    #pragma unroll
    for (int i = 0; i < 3; i++) {
        v[i] = src[tid + 256 * i];
        sum += v[i]; sq += v[i] * v[i];
    }
    block_reduce2(sum, sq, s1, s2);
    float mu = sum * (1.f / 768.f);
    float var = sq * (1.f / 768.f) - mu * mu;
    float rstd = rsqrtf(var + 1e-5f);

    float w[3]; sum = 0.f; sq = 0.f;
    #pragma unroll
    for (int i = 0; i < 3; i++) {
        int idx = tid + 256 * i;
        w[i] = (v[i] - mu) * rstd * g1[idx] + b1[idx];
        g_xaug[(long long)row * D_MODEL + idx] = w[i];
        sum += w[i]; sq += w[i] * w[i];
    }
    block_reduce2(sum, sq, s1, s2);
    float mu2 = sum * (1.f / 768.f);
    float var2 = sq * (1.f / 768.f) - mu2 * mu2;
    float rstd2 = rsqrtf(var2 + 1e-5f);
    #pragma unroll
    for (int i = 0; i < 3; i++) {
        int idx = tid + 256 * i;
        g_h[(long long)row * D_MODEL + idx] = (w[i] - mu2) * rstd2 * ga[idx] + ba[idx];
    }
}

__global__ void ln_kernel(const float* __restrict__ src, float* __restrict__ dst,
                          const float* __restrict__ g, const float* __restrict__ b) {
    __shared__ float s1[256], s2[256];
    int row = blockIdx.x;
    int tid = threadIdx.x;
    const float* p = src + (long long)row * D_MODEL;
    float v[3]; float sum = 0.f, sq = 0.f;
    #pragma unroll
    for (int i = 0; i < 3; i++) {
        v[i] = p[tid + 256 * i];
        sum += v[i]; sq += v[i] * v[i];
    }
    block_reduce2(sum, sq, s1, s2);
    float mu = sum * (1.f / 768.f);
    float var = sq * (1.f / 768.f) - mu * mu;
    float rstd = rsqrtf(var + 1e-5f);
    #pragma unroll
    for (int i = 0; i < 3; i++) {
        int idx = tid + 256 * i;
        dst[(long long)row * D_MODEL + idx] = (v[i] - mu) * rstd * g[idx] + b[idx];
    }
}

// ---------------- launch ----------------
extern "C" void kernel_launch(void* const* d_in, const int* in_sizes, int n_in,
                              void* d_out, int out_size) {
    const float* x        = (const float*)d_in[0];
    const float* memory   = (const float*)d_in[1];
    const float* ln_att_g = (const float*)d_in[2];
    const float* ln_att_b = (const float*)d_in[3];
    const float* w_qkv    = (const float*)d_in[4];
    const float* w_out    = (const float*)d_in[5];
    const float* b_out    = (const float*)d_in[6];
    const float* ln1_g    = (const float*)d_in[7];
    const float* ln1_b    = (const float*)d_in[8];
    const float* ln2_g    = (const float*)d_in[9];
    const float* ln2_b    = (const float*)d_in[10];
    const float* w1       = (const float*)d_in[11];
    const float* b1       = (const float*)d_in[12];
    const float* w2       = (const float*)d_in[13];
    const float* b2       = (const float*)d_in[14];
    float* out = (float*)d_out;

    float *xaug, *h, *qkv, *ctx, *y2, *ff;
    cudaGetSymbolAddress((void**)&xaug, g_xaug);
    cudaGetSymbolAddress((void**)&h,    g_h);
    cudaGetSymbolAddress((void**)&qkv,  g_qkv);
    cudaGetSymbolAddress((void**)&ctx,  g_ctx);
    cudaGetSymbolAddress((void**)&y2,   g_y2);
    cudaGetSymbolAddress((void**)&ff,   g_ff);

    const int FLASH_SMEM = (128 * PADQ + 4 * 64 * PADQ) * 4;  // 104448 B
    cudaFuncSetAttribute(flash_attn, cudaFuncAttributeMaxDynamicSharedMemorySize, FLASH_SMEM);

    // 1) x_aug = ln1(concat(mem, x)); h = ln_att(x_aug)
    ln_build_kernel<<<ROWS, 256>>>(x, memory, ln1_g, ln1_b, ln_att_g, ln_att_b);

    // 2) qkv = h @ w_qkv^T
    mma_gemm<false, false, false, false><<<dim3(18, 49), 256>>>(
        h, w_qkv, qkv, nullptr, nullptr, nullptr,
        ROWS, 3 * D_MODEL, D_MODEL, D_MODEL, D_MODEL, 3 * D_MODEL, 1.f);

    // 3-5) fused attention -> ctx
    flash_attn<<<dim3(13, 48), 256, FLASH_SMEM>>>(qkv, ctx);

    // 6) xaug += ctx @ w_out^T + b_out
    mma_gemm<true, true, false, false><<<dim3(6, 49), 256>>>(
        ctx, w_out, xaug, b_out, xaug, nullptr,
        ROWS, D_MODEL, D_MODEL, D_MODEL, D_MODEL, D_MODEL, 1.f);

    // 7) y2 = ln2(xaug)
    ln_kernel<<<ROWS, 256>>>(xaug, y2, ln2_g, ln2_b);

    // 8) ff = silu(y2 @ w1^T + b1)
    mma_gemm<true, false, true, false><<<dim3(24, 49), 256>>>(
        y2, w1, ff, b1, nullptr, nullptr,
        ROWS, D_FF, D_MODEL, D_MODEL, D_MODEL, D_FF, 1.f);

    // 9) xaug += ff @ w2^T + b2 ; scatter x-rows to out
    mma_gemm<true, true, false, true><<<dim3(6, 49), 256>>>(
        ff, w2, xaug, b2, xaug, out,
        ROWS, D_MODEL, D_FF, D_FF, D_FF, D_MODEL, 1.f);
}

// round 10
// speedup vs baseline: 1.8057x; 1.6116x over previous
#include <cuda_runtime.h>
#include <cuda_fp16.h>
#include <math.h>
#include <stdint.h>

#define L_TOT 1568
#define T_LEN 784
#define D_MODEL 768
#define N_HEADS 12
#define DIM_HEAD 64
#define D_FF 3072
#define BATCH 4
#define ROWS (BATCH * L_TOT)          // 6272
#define NPATCH 196

// ---------------- scratch ----------------
__device__ float  g_xaug[ROWS * D_MODEL];          // residual stream (f32)
__device__ __half g_h[ROWS * D_MODEL];             // ln_att output (h16)
__device__ __half g_qkv[ROWS * 3 * D_MODEL];       // qkv (h16)
__device__ __half g_ctx[ROWS * D_MODEL];           // attention context (h16)
__device__ __half g_y2[ROWS * D_MODEL];            // ln2 output (h16)
__device__ __half g_ff[ROWS * D_FF];               // ff hidden (h16)
__device__ __half g_whalf[7077888];                // wqkv|wout|w1|w2 in h16

// ---------------- helpers ----------------
__device__ __forceinline__ unsigned smem_u32(const void* p) {
    unsigned r;
    asm("{ .reg .u64 t; cvta.to.shared.u64 t, %1; cvt.u32.u64 %0, t; }" : "=r"(r) : "l"(p));
    return r;
}
__device__ __forceinline__ void cp16(unsigned dst, const void* src, bool valid) {
    int sz = valid ? 16 : 0;
    asm volatile("cp.async.cg.shared.global [%0], [%1], 16, %2;" :: "r"(dst), "l"(src), "r"(sz));
}
__device__ __forceinline__ void mma_f16(float4& d, const unsigned a[4], unsigned b0, unsigned b1) {
    asm volatile(
        "mma.sync.aligned.m16n8k16.row.col.f32.f16.f16.f32 "
        "{%0,%1,%2,%3}, {%4,%5,%6,%7}, {%8,%9}, {%0,%1,%2,%3};"
        : "+f"(d.x), "+f"(d.y), "+f"(d.z), "+f"(d.w)
        : "r"(a[0]), "r"(a[1]), "r"(a[2]), "r"(a[3]), "r"(b0), "r"(b1));
}

// ---------------- fp16 tensor-core GEMM ----------------
// C[m,n] = sum_k A[m,k] * B[n,k]  (A [M,K] h16 row-major, B [N,K] h16 row-major)
// M,N multiples of 128; K multiple of 32. f32 accumulate.
// Epilogue: +bias; silu; +res(f32); C as f32 or h16; OUTW scatter.
#define SH 40   // smem row stride in halves (32 data + 8 pad)
template <bool BIAS, bool RES, bool SILU, bool OUTW, bool HOUT>
__global__ void __launch_bounds__(256, 1)
hgemm(const __half* __restrict__ A, const __half* __restrict__ B,
      void* __restrict__ Cv, const float* __restrict__ bias, const float* __restrict__ res,
      float* __restrict__ out2,
      int M, int N, int K, int lda, int ldb, int ldc) {
    const int NT = 8;
    __shared__ __half As[2][128 * SH];
    __shared__ __half Bs[2][128 * SH];

    int tid = threadIdx.x;
    int m0 = blockIdx.y * 128, n0 = blockIdx.x * 128;
    int warp = tid >> 5, lane = tid & 31;
    int wm = warp & 3, wn = warp >> 2;
    int mw = m0 + wm * 32;
    int nw = n0 + wn * 64;
    int g = lane >> 2, tg = lane & 3;

    float4 acc[2][NT];
    #pragma unroll
    for (int i = 0; i < 2; i++)
        #pragma unroll
        for (int j = 0; j < NT; j++) acc[i][j] = make_float4(0.f, 0.f, 0.f, 0.f);

    unsigned sA = smem_u32(As), sB = smem_u32(Bs);

    auto load_stage = [&](int ks, int buf) {   // ks in halves, 32 per stage
        #pragma unroll
        for (int i = 0; i < 2; i++) {
            int c = tid + i * 256;             // 0..511
            int row = c >> 2, kc = (c & 3) << 3;
            unsigned dst = sA + (buf * 128 * SH + row * SH + kc) * 2;
            cp16(dst, A + (long long)(m0 + row) * lda + ks + kc, true);
        }
        #pragma unroll
        for (int i = 0; i < 2; i++) {
            int c = tid + i * 256;
            int row = c >> 2, kc = (c & 3) << 3;
            unsigned dst = sB + (buf * 128 * SH + row * SH + kc) * 2;
            cp16(dst, B + (long long)(n0 + row) * ldb + ks + kc, true);
        }
    };

    auto compute = [&](int buf) {
        const __half* Ap = &As[buf][0];
        const __half* Bp = &Bs[buf][0];
        #pragma unroll
        for (int ks = 0; ks < 2; ks++) {       // two k16 steps per 32-half stage
            int ko = ks * 16 + 2 * tg;
            unsigned af[2][4];
            #pragma unroll
            for (int i = 0; i < 2; i++) {
                const __half* p = Ap + (wm * 32 + i * 16 + g) * SH + ko;
                af[i][0] = *(const unsigned*)p;
                af[i][1] = *(const unsigned*)(p + 8 * SH);
                af[i][2] = *(const unsigned*)(p + 8);
                af[i][3] = *(const unsigned*)(p + 8 * SH + 8);
            }
            #pragma unroll
            for (int j = 0; j < NT; j++) {
                const __half* p = Bp + (wn * 64 + j * 8 + g) * SH + ko;
                unsigned b0 = *(const unsigned*)p;
                unsigned b1 = *(const unsigned*)(p + 8);
                #pragma unroll
                for (int i = 0; i < 2; i++)
                    mma_f16(acc[i][j], af[i], b0, b1);
            }
        }
    };

    int numK = K >> 5;
    load_stage(0, 0);
    asm volatile("cp.async.commit_group;");
    for (int it = 0; it < numK; it++) {
        if (it + 1 < numK) {
            load_stage((it + 1) << 5, (it + 1) & 1);
            asm volatile("cp.async.commit_group;");
            asm volatile("cp.async.wait_group 1;");
        } else {
            asm volatile("cp.async.wait_group 0;");
        }
        __syncthreads();
        compute(it & 1);
        __syncthreads();
    }

    float* Cf = (float*)Cv;
    __half* Ch = (__half*)Cv;
    #pragma unroll
    for (int i = 0; i < 2; i++) {
        #pragma unroll
        for (int half_ = 0; half_ < 2; half_++) {
            int r = mw + i * 16 + g + half_ * 8;
            long long base = (long long)r * ldc;
            int bb = 0, l = 0;
            if (OUTW) { bb = r / L_TOT; l = r - bb * L_TOT; }
            #pragma unroll
            for (int j = 0; j < NT; j++) {
                float w0 = half_ ? acc[i][j].z : acc[i][j].x;
                float w1 = half_ ? acc[i][j].w : acc[i][j].y;
                int c0 = nw + j * 8 + tg * 2;
                if (BIAS) { w0 += bias[c0]; w1 += bias[c0 + 1]; }
                if (SILU) {
                    w0 = w0 / (1.f + expf(-w0));
                    w1 = w1 / (1.f + expf(-w1));
                }
                if (RES) { w0 += res[base + c0]; w1 += res[base + c0 + 1]; }
                if (HOUT) {
                    *(__half2*)(Ch + base + c0) = __floats2half2_rn(w0, w1);
                } else {
                    Cf[base + c0] = w0;
                    Cf[base + c0 + 1] = w1;
                }
                if (OUTW && l >= T_LEN) {
                    long long ob = ((long long)bb * T_LEN + (l - T_LEN)) * D_MODEL;
                    out2[ob + c0] = w0;
                    out2[ob + c0 + 1] = w1;
                }
            }
        }
    }
}

// ---------------- weight f32 -> f16 conversion ----------------
__global__ void cvt_half_kernel(const float* __restrict__ src, __half* __restrict__ dst, int n2) {
    int i = blockIdx.x * 256 + threadIdx.x;
    if (i >= n2) return;
    float2 v = ((const float2*)src)[i];
    ((__half2*)dst)[i] = __floats2half2_rn(v.x, v.y);
}

// ---------------- fused flash attention (fp16 mma) ----------------
#define PADH 72
__global__ void __launch_bounds__(256, 2)
flash_attn(const __half* __restrict__ qkv, __half* __restrict__ ctx) {
    extern __shared__ __half smh[];
    __half* sP = smh;                       // 128 * PADH
    __half* sK = smh + 128 * PADH;          // 2 * 64 * PADH
    __half* sV = sK + 2 * 64 * PADH;        // 2 * 64 * PADH

    int tid = threadIdx.x;
    int warp = tid >> 5, lane = tid & 31;
    int g = lane >> 2, tg = lane & 3;
    int bh = blockIdx.y;
    int b = bh / N_HEADS, h = bh - b * N_HEADS;
    int m0 = blockIdx.x * 128;

    const __half* base = qkv + (long long)b * L_TOT * (3 * D_MODEL);
    const __half* Qp = base + h * 64;
    const __half* Kp = base + D_MODEL + h * 64;
    const __half* Vp = base + 2 * D_MODEL + h * 64;

    // stage Q tile (128 x 64 halves)
    #pragma unroll
    for (int i = 0; i < 4; i++) {
        int c = tid + i * 256;                 // 0..1023
        int m = c >> 3, q = (c & 7) << 3;      // 8 halves per chunk
        unsigned dst = smem_u32(sP + m * PADH + q);
        cp16(dst, Qp + (long long)(m0 + m) * (3 * D_MODEL) + q, (m0 + m) < L_TOT);
    }
    asm volatile("cp.async.commit_group;");
    asm volatile("cp.async.wait_group 0;");
    __syncthreads();

    unsigned qf[4][4];
    {
        const __half* qp = sP + (warp * 16) * PADH;
        #pragma unroll
        for (int ks = 0; ks < 4; ks++) {
            const __half* p = qp + g * PADH + 16 * ks + 2 * tg;
            qf[ks][0] = *(const unsigned*)p;
            qf[ks][1] = *(const unsigned*)(p + 8 * PADH);
            qf[ks][2] = *(const unsigned*)(p + 8);
            qf[ks][3] = *(const unsigned*)(p + 8 * PADH + 8);
        }
    }
    __syncthreads();   // done reading Q before sP reused for P

    int r0 = m0 + warp * 16 + g;
    int r1 = r0 + 8;
    int km0 = (r0 < T_LEN) ? L_TOT : ((r0 / NPATCH) + 1) * NPATCH;
    int km1 = (r1 < T_LEN) ? L_TOT : ((r1 / NPATCH) + 1) * NPATCH;

    float mrow0 = -1e30f, mrow1 = -1e30f, lrow0 = 0.f, lrow1 = 0.f;
    float4 accO[8];
    #pragma unroll
    for (int j = 0; j < 8; j++) accO[j] = make_float4(0.f, 0.f, 0.f, 0.f);

    int rlast = min(m0 + 127, L_TOT - 1);
    int kend = (m0 < T_LEN) ? L_TOT : ((rlast / NPATCH) + 1) * NPATCH;
    int ntiles = (kend + 63) >> 6;

    auto loadKV = [&](int t, int buf) {
        int n0t = t * 64;
        #pragma unroll
        for (int i = 0; i < 2; i++) {
            int c = tid + i * 256;             // 0..511
            int kv = c >> 3, q = (c & 7) << 3;
            bool ok = (n0t + kv) < L_TOT;
            long long goff = (long long)(n0t + kv) * (3 * D_MODEL) + q;
            cp16(smem_u32(sK + buf * 64 * PADH + kv * PADH + q), Kp + goff, ok);
            cp16(smem_u32(sV + buf * 64 * PADH + kv * PADH + q), Vp + goff, ok);
        }
    };

    loadKV(0, 0);
    asm volatile("cp.async.commit_group;");

    __half* pp = sP + (warp * 16) * PADH;

    for (int t = 0; t < ntiles; t++) {
        int buf = t & 1;
        if (t + 1 < ntiles) {
            loadKV(t + 1, buf ^ 1);
            asm volatile("cp.async.commit_group;");
            asm volatile("cp.async.wait_group 1;");
        } else {
            asm volatile("cp.async.wait_group 0;");
        }
        __syncthreads();

        // S = Q @ K^T  (k = d = 64, 4 k16 steps)
        float4 s[8];
        #pragma unroll
        for (int j = 0; j < 8; j++) s[j] = make_float4(0.f, 0.f, 0.f, 0.f);
        const __half* kb = sK + buf * 64 * PADH;
        #pragma unroll
        for (int j = 0; j < 8; j++) {
            const __half* kr = kb + (8 * j + g) * PADH + 2 * tg;
            #pragma unroll
            for (int ks = 0; ks < 4; ks++) {
                unsigned b0 = *(const unsigned*)(kr + 16 * ks);
                unsigned b1 = *(const unsigned*)(kr + 16 * ks + 8);
                mma_f16(s[j], qf[ks], b0, b1);
            }
        }

        // scale + mask + online softmax
        float tmax0 = -1e30f, tmax1 = -1e30f;
        #pragma unroll
        for (int j = 0; j < 8; j++) {
            int c0 = t * 64 + 8 * j + 2 * tg;
            int c1 = c0 + 1;
            s[j].x = (c0 < km0) ? s[j].x * 0.125f : -1e30f;
            s[j].y = (c1 < km0) ? s[j].y * 0.125f : -1e30f;
            s[j].z = (c0 < km1) ? s[j].z * 0.125f : -1e30f;
            s[j].w = (c1 < km1) ? s[j].w * 0.125f : -1e30f;
            tmax0 = fmaxf(tmax0, fmaxf(s[j].x, s[j].y));
            tmax1 = fmaxf(tmax1, fmaxf(s[j].z, s[j].w));
        }
        tmax0 = fmaxf(tmax0, __shfl_xor_sync(0xffffffffu, tmax0, 1));
        tmax0 = fmaxf(tmax0, __shfl_xor_sync(0xffffffffu, tmax0, 2));
        tmax1 = fmaxf(tmax1, __shfl_xor_sync(0xffffffffu, tmax1, 1));
        tmax1 = fmaxf(tmax1, __shfl_xor_sync(0xffffffffu, tmax1, 2));

        float mn0 = fmaxf(mrow0, tmax0), mn1 = fmaxf(mrow1, tmax1);
        float al0 = __expf(mrow0 - mn0), al1 = __expf(mrow1 - mn1);
        mrow0 = mn0; mrow1 = mn1;

        float rs0 = 0.f, rs1 = 0.f;
        #pragma unroll
        for (int j = 0; j < 8; j++) {
            s[j].x = __expf(s[j].x - mn0);
            s[j].y = __expf(s[j].y - mn0);
            s[j].z = __expf(s[j].z - mn1);
            s[j].w = __expf(s[j].w - mn1);
            rs0 += s[j].x + s[j].y;
            rs1 += s[j].z + s[j].w;
            *(__half2*)&pp[g * PADH + 8 * j + 2 * tg] = __floats2half2_rn(s[j].x, s[j].y);
            *(__half2*)&pp[(g + 8) * PADH + 8 * j + 2 * tg] = __floats2half2_rn(s[j].z, s[j].w);
        }
        rs0 += __shfl_xor_sync(0xffffffffu, rs0, 1);
        rs0 += __shfl_xor_sync(0xffffffffu, rs0, 2);
        rs1 += __shfl_xor_sync(0xffffffffu, rs1, 1);
        rs1 += __shfl_xor_sync(0xffffffffu, rs1, 2);
        lrow0 = lrow0 * al0 + rs0;
        lrow1 = lrow1 * al1 + rs1;

        #pragma unroll
        for (int j = 0; j < 8; j++) {
            accO[j].x *= al0; accO[j].y *= al0;
            accO[j].z *= al1; accO[j].w *= al1;
        }
        __syncwarp();

        // O += P @ V   (k = kv = 64, 4 k16 steps; B packed from V rows)
        const __half* vb = sV + buf * 64 * PADH;
        #pragma unroll
        for (int ks = 0; ks < 4; ks++) {
            unsigned af[4];
            const __half* pa = pp + g * PADH + 16 * ks + 2 * tg;
            af[0] = *(const unsigned*)pa;
            af[1] = *(const unsigned*)(pa + 8 * PADH);
            af[2] = *(const unsigned*)(pa + 8);
            af[3] = *(const unsigned*)(pa + 8 * PADH + 8);
            const __half* v0a = vb + (16 * ks + 2 * tg) * PADH;
            const __half* v0b = v0a + PADH;
            const __half* v1a = v0a + 8 * PADH;
            const __half* v1b = v1a + PADH;
            #pragma unroll
            for (int j = 0; j < 8; j++) {
                int n = 8 * j + g;
                unsigned b0 = (unsigned)*(const unsigned short*)(v0a + n)
                            | ((unsigned)*(const unsigned short*)(v0b + n) << 16);
                unsigned b1 = (unsigned)*(const unsigned short*)(v1a + n)
                            | ((unsigned)*(const unsigned short*)(v1b + n) << 16);
                mma_f16(accO[j], af, b0, b1);
            }
        }
        __syncthreads();
    }

    float inv0 = 1.f / lrow0, inv1 = 1.f / lrow1;
    if (r0 < L_TOT) {
        __half* op = ctx + ((long long)b * L_TOT + r0) * D_MODEL + h * 64;
        #pragma unroll
        for (int j = 0; j < 8; j++)
            *(__half2*)&op[8 * j + 2 * tg] = __floats2half2_rn(accO[j].x * inv0, accO[j].y * inv0);
    }
    if (r1 < L_TOT) {
        __half* op = ctx + ((long long)b * L_TOT + r1) * D_MODEL + h * 64;
        #pragma unroll
        for (int j = 0; j < 8; j++)
            *(__half2*)&op[8 * j + 2 * tg] = __floats2half2_rn(accO[j].z * inv1, accO[j].w * inv1);
    }
}

// ---------------- layernorms ----------------
__device__ __forceinline__ void block_reduce2(float& a, float& b, float* s1, float* s2) {
    int tid = threadIdx.x;
    s1[tid] = a; s2[tid] = b; __syncthreads();
    #pragma unroll
    for (int s = 128; s; s >>= 1) {
        if (tid < s) { s1[tid] += s1[tid + s]; s2[tid] += s2[tid + s]; }
        __syncthreads();
    }
    a = s1[0]; b = s2[0]; __syncthreads();
}

__global__ void ln_build_kernel(const float* __restrict__ x,
                                const float* __restrict__ mem,
                                const float* __restrict__ g1, const float* __restrict__ b1,
                                const float* __restrict__ ga, const float* __restrict__ ba) {
    __shared__ float s1[256], s2[256];
    int row = blockIdx.x;
    int b = row / L_TOT;
    int l = row - b * L_TOT;
    const float* src = (l < T_LEN)
        ? mem + ((long long)b * 1024 + l) * D_MODEL
        : x   + ((long long)b * T_LEN + (l - T_LEN)) * D_MODEL;
    int tid = threadIdx.x;
    float v[3]; float sum = 0.f, sq = 0.f;
    #pragma unroll
    for (int i = 0; i < 3; i++) {
        v[i] = src[tid + 256 * i];
        sum += v[i]; sq += v[i] * v[i];
    }
    block_reduce2(sum, sq, s1, s2);
    float mu = sum * (1.f / 768.f);
    float var = sq * (1.f / 768.f) - mu * mu;
    float rstd = rsqrtf(var + 1e-5f);

    float w[3]; sum = 0.f; sq = 0.f;
    #pragma unroll
    for (int i = 0; i < 3; i++) {
        int idx = tid + 256 * i;
        w[i] = (v[i] - mu) * rstd * g1[idx] + b1[idx];
        g_xaug[(long long)row * D_MODEL + idx] = w[i];
        sum += w[i]; sq += w[i] * w[i];
    }
    block_reduce2(sum, sq, s1, s2);
    float mu2 = sum * (1.f / 768.f);
    float var2 = sq * (1.f / 768.f) - mu2 * mu2;
    float rstd2 = rsqrtf(var2 + 1e-5f);
    #pragma unroll
    for (int i = 0; i < 3; i++) {
        int idx = tid + 256 * i;
        g_h[(long long)row * D_MODEL + idx] =
            __float2half((w[i] - mu2) * rstd2 * ga[idx] + ba[idx]);
    }
}

__global__ void ln_kernel(const float* __restrict__ src, __half* __restrict__ dst,
                          const float* __restrict__ g, const float* __restrict__ b) {
    __shared__ float s1[256], s2[256];
    int row = blockIdx.x;
    int tid = threadIdx.x;
    const float* p = src + (long long)row * D_MODEL;
    float v[3]; float sum = 0.f, sq = 0.f;
    #pragma unroll
    for (int i = 0; i < 3; i++) {
        v[i] = p[tid + 256 * i];
        sum += v[i]; sq += v[i] * v[i];
    }
    block_reduce2(sum, sq, s1, s2);
    float mu = sum * (1.f / 768.f);
    float var = sq * (1.f / 768.f) - mu * mu;
    float rstd = rsqrtf(var + 1e-5f);
    #pragma unroll
    for (int i = 0; i < 3; i++) {
        int idx = tid + 256 * i;
        dst[(long long)row * D_MODEL + idx] =
            __float2half((v[i] - mu) * rstd * g[idx] + b[idx]);
    }
}

// ---------------- launch ----------------
extern "C" void kernel_launch(void* const* d_in, const int* in_sizes, int n_in,
                              void* d_out, int out_size) {
    const float* x        = (const float*)d_in[0];
    const float* memory   = (const float*)d_in[1];
    const float* ln_att_g = (const float*)d_in[2];
    const float* ln_att_b = (const float*)d_in[3];
    const float* w_qkv    = (const float*)d_in[4];
    const float* w_out    = (const float*)d_in[5];
    const float* b_out    = (const float*)d_in[6];
    const float* ln1_g    = (const float*)d_in[7];
    const float* ln1_b    = (const float*)d_in[8];
    const float* ln2_g    = (const float*)d_in[9];
    const float* ln2_b    = (const float*)d_in[10];
    const float* w1       = (const float*)d_in[11];
    const float* b1       = (const float*)d_in[12];
    const float* w2       = (const float*)d_in[13];
    const float* b2       = (const float*)d_in[14];
    float* out = (float*)d_out;

    float* xaug;
    __half *h, *qkv, *ctx, *y2, *ff, *wh;
    cudaGetSymbolAddress((void**)&xaug, g_xaug);
    cudaGetSymbolAddress((void**)&h,    g_h);
    cudaGetSymbolAddress((void**)&qkv,  g_qkv);
    cudaGetSymbolAddress((void**)&ctx,  g_ctx);
    cudaGetSymbolAddress((void**)&y2,   g_y2);
    cudaGetSymbolAddress((void**)&ff,   g_ff);
    cudaGetSymbolAddress((void**)&wh,   g_whalf);

    __half* wqkv_h = wh;                 // 2304*768 = 1769472
    __half* wout_h = wh + 1769472;       // 768*768  = 589824
    __half* w1_h   = wh + 2359296;       // 3072*768 = 2359296
    __half* w2_h   = wh + 4718592;       // 768*3072 = 2359296

    const int FLASH_SMEM = (128 * PADH + 4 * 64 * PADH) * 2;  // 55296 B
    cudaFuncSetAttribute(flash_attn, cudaFuncAttributeMaxDynamicSharedMemorySize, FLASH_SMEM);

    // 0) convert weights to h16
    cvt_half_kernel<<<3456, 256>>>(w_qkv, wqkv_h, 884736);
    cvt_half_kernel<<<1152, 256>>>(w_out, wout_h, 294912);
    cvt_half_kernel<<<4608, 256>>>(w1,    w1_h,   1179648);
    cvt_half_kernel<<<4608, 256>>>(w2,    w2_h,   1179648);

    // 1) x_aug = ln1(concat(mem, x)) [f32]; h = ln_att(x_aug) [h16]
    ln_build_kernel<<<ROWS, 256>>>(x, memory, ln1_g, ln1_b, ln_att_g, ln_att_b);

    // 2) qkv = h @ w_qkv^T  [h16]
    hgemm<false, false, false, false, true><<<dim3(18, 49), 256>>>(
        h, wqkv_h, qkv, nullptr, nullptr, nullptr,
        ROWS, 3 * D_MODEL, D_MODEL, D_MODEL, D_MODEL, 3 * D_MODEL);

    // 3-5) fused attention -> ctx [h16]
    flash_attn<<<dim3(13, 48), 256, FLASH_SMEM>>>(qkv, ctx);

    // 6) xaug += ctx @ w_out^T + b_out  [f32]
    hgemm<true, true, false, false, false><<<dim3(6, 49), 256>>>(
        ctx, wout_h, xaug, b_out, xaug, nullptr,
        ROWS, D_MODEL, D_MODEL, D_MODEL, D_MODEL, D_MODEL);

    // 7) y2 = ln2(xaug)  [h16]
    ln_kernel<<<ROWS, 256>>>(xaug, y2, ln2_g, ln2_b);

    // 8) ff = silu(y2 @ w1^T + b1)  [h16]
    hgemm<true, false, true, false, true><<<dim3(24, 49), 256>>>(
        y2, w1_h, ff, b1, nullptr, nullptr,
        ROWS, D_FF, D_MODEL, D_MODEL, D_MODEL, D_FF);

    // 9) xaug += ff @ w2^T + b2 ; scatter x-rows to out  [f32]
    hgemm<true, true, false, true, false><<<dim3(6, 49), 256>>>(
        ff, w2_h, xaug, b2, xaug, out,
        ROWS, D_MODEL, D_FF, D_FF, D_FF, D_MODEL);
}